// round 1
// baseline (speedup 1.0000x reference)
#include <cuda_runtime.h>
#include <cstdint>

#define NNODES 262144
#define ROWS 256
#define NT 256
#define AP 264   // transposed activation tile row stride (floats), 64 x AP
#define WP 68    // weight buffer row stride (floats)

// Scratch (static device globals: allowed; no runtime allocation)
__device__ float g_rec[(size_t)NNODES * 64];
__device__ float g_u[(size_t)NNODES * 64];
__device__ int   g_inv[(size_t)NNODES * 8];

static __device__ __forceinline__ float4 ld4(const float* p) { return *(const float4*)p; }
static __device__ __forceinline__ void st4(float* p, float4 v) { *(float4*)p = v; }

static __device__ __forceinline__ void zero_acc(float acc[8][8]) {
#pragma unroll
    for (int i = 0; i < 8; i++)
#pragma unroll
        for (int j = 0; j < 8; j++) acc[i][j] = 0.f;
}

// C[256x64] += At(k-major [64][AP]) * Wb([64][WP]); 8x8 frag per thread.
static __device__ __forceinline__ void gemm64(const float* __restrict__ At,
                                              const float* __restrict__ Wb,
                                              int ty, int tx, float acc[8][8]) {
    const float* ap = At + ty * 8;
    const float* wp = Wb + tx * 8;
#pragma unroll 4
    for (int k = 0; k < 64; k++) {
        float4 a0 = ld4(ap + k * AP);
        float4 a1 = ld4(ap + k * AP + 4);
        float4 w0 = ld4(wp + k * WP);
        float4 w1 = ld4(wp + k * WP + 4);
        float av[8] = {a0.x, a0.y, a0.z, a0.w, a1.x, a1.y, a1.z, a1.w};
        float wv[8] = {w0.x, w0.y, w0.z, w0.w, w1.x, w1.y, w1.z, w1.w};
#pragma unroll
        for (int i = 0; i < 8; i++)
#pragma unroll
            for (int j = 0; j < 8; j++)
                acc[i][j] += av[i] * wv[j];
    }
}

// Load a [256 x 64] row-major global tile and store transposed (k-major) into smem.
static __device__ __forceinline__ void load_tileT(float* Xt, const float* __restrict__ src,
                                                  int base, int tid) {
#pragma unroll
    for (int q = 0; q < 16; q++) {
        int lin = (q * NT + tid) * 4;
        int row = lin >> 6, k = lin & 63;
        float4 v = ld4(src + (size_t)(base + row) * 64 + k);
        Xt[(k + 0) * AP + row] = v.x;
        Xt[(k + 1) * AP + row] = v.y;
        Xt[(k + 2) * AP + row] = v.z;
        Xt[(k + 3) * AP + row] = v.w;
    }
}

static __device__ __forceinline__ void load_w(float* Wb, const float* __restrict__ W, int K, int tid) {
    for (int lin = tid; lin < K * 64; lin += NT)
        Wb[(lin >> 6) * WP + (lin & 63)] = W[lin];
}

// y = prelu(acc + b, a), stored transposed (k-major) into Dst.
static __device__ __forceinline__ void epi_prelu_T(float acc[8][8], const float* sB, const float* sA,
                                                   float* Dst, int ty, int tx) {
#pragma unroll
    for (int j = 0; j < 8; j++) {
        int c = tx * 8 + j;
        float b = sB[c], a = sA[c];
        float t0[8];
#pragma unroll
        for (int i = 0; i < 8; i++) {
            float v = acc[i][j] + b;
            t0[i] = v >= 0.f ? v : a * v;
        }
        st4(&Dst[c * AP + ty * 8],     make_float4(t0[0], t0[1], t0[2], t0[3]));
        st4(&Dst[c * AP + ty * 8 + 4], make_float4(t0[4], t0[5], t0[6], t0[7]));
    }
}

// y = acc + b + Res (residual read transposed); optionally also store transposed into AlsoT;
// always store row-major to gOut (coalesced float4 stores).
static __device__ __forceinline__ void epi_res_gstore(float acc[8][8], const float* sB,
                                                      const float* Res, float* AlsoT,
                                                      float* __restrict__ gOut, int base,
                                                      int ty, int tx) {
#pragma unroll
    for (int j = 0; j < 8; j++) {
        int c = tx * 8 + j;
        float b = sB[c];
        float4 r0 = ld4(&Res[c * AP + ty * 8]);
        float4 r1 = ld4(&Res[c * AP + ty * 8 + 4]);
        acc[0][j] += b + r0.x; acc[1][j] += b + r0.y; acc[2][j] += b + r0.z; acc[3][j] += b + r0.w;
        acc[4][j] += b + r1.x; acc[5][j] += b + r1.y; acc[6][j] += b + r1.z; acc[7][j] += b + r1.w;
        if (AlsoT) {
            st4(&AlsoT[c * AP + ty * 8],     make_float4(acc[0][j], acc[1][j], acc[2][j], acc[3][j]));
            st4(&AlsoT[c * AP + ty * 8 + 4], make_float4(acc[4][j], acc[5][j], acc[6][j], acc[7][j]));
        }
    }
#pragma unroll
    for (int i = 0; i < 8; i++) {
        int r = ty * 8 + i;
        st4(&gOut[(size_t)(base + r) * 64 + tx * 8],
            make_float4(acc[i][0], acc[i][1], acc[i][2], acc[i][3]));
        st4(&gOut[(size_t)(base + r) * 64 + tx * 8 + 4],
            make_float4(acc[i][4], acc[i][5], acc[i][6], acc[i][7]));
    }
}

// ---------------- K0: inverse map of sel_idx ----------------
__global__ void k0_inv(const int* __restrict__ sel, int M) {
    int m = blockIdx.x * 256 + threadIdx.x;
    if (m < M) g_inv[sel[m]] = m;
}

// ---------------- K1: dec resblock + oct + upsample front (u) ----------------
__global__ __launch_bounds__(NT, 1)
void k1_dec_up(const float* __restrict__ X, const int* __restrict__ bin,
               const float* __restrict__ Wd1, const float* __restrict__ bd1, const float* __restrict__ ad,
               const float* __restrict__ Wd2, const float* __restrict__ bd2,
               const float* __restrict__ Wu1, const float* __restrict__ bu1, const float* __restrict__ au1,
               const float* __restrict__ Wu2, const float* __restrict__ bu2, const float* __restrict__ au2,
               const float* __restrict__ Wu3, const float* __restrict__ bu3,
               float* __restrict__ oct_out) {
    extern __shared__ float sm[];
    float* Xt = sm;              // [64][AP]
    float* Ht = Xt + 64 * AP;    // [64][AP]
    float* Bt = Ht + 64 * AP;    // [8][AP]  bin * 256 (transposed)
    float* Wb = Bt + 8 * AP;     // [72][WP]
    float* sB = Wb + 72 * WP;    // 64
    float* sA = sB + 64;         // 64

    int tid = threadIdx.x;
    int ty = tid >> 3, tx = tid & 7;
    int base = blockIdx.x * ROWS;

    load_tileT(Xt, X, base, tid);
#pragma unroll
    for (int q = 0; q < 8; q++) {
        int lin = q * NT + tid;
        Bt[(lin & 7) * AP + (lin >> 3)] = (float)(bin[(size_t)base * 8 + lin] << 8);
    }
    load_w(Wb, Wd1, 64, tid);
    if (tid < 64) { sB[tid] = bd1[tid]; sA[tid] = ad[tid]; }
    __syncthreads();

    // cur_oct (one row per thread)
    {
        int oct = -1;
#pragma unroll
        for (int j = 0; j < 8; j++)
            if (Bt[j * AP + tid] != 0.f) oct += (1 << j);
        oct_out[base + tid] = (float)oct;
    }

    float acc[8][8];
    // stage 1: h = prelu(X@Wd1 + b) -> Ht
    zero_acc(acc);
    gemm64(Xt, Wb, ty, tx, acc);
    epi_prelu_T(acc, sB, sA, Ht, ty, tx);
    __syncthreads();
    load_w(Wb, Wd2, 64, tid);
    if (tid < 64) sB[tid] = bd2[tid];
    __syncthreads();
    // stage 2: rec = X + h@Wd2 + b -> Xt (in place) and g_rec
    zero_acc(acc);
    gemm64(Ht, Wb, ty, tx, acc);
    epi_res_gstore(acc, sB, Xt, Xt, g_rec, base, ty, tx);
    __syncthreads();
    load_w(Wb, Wu1, 72, tid);
    if (tid < 64) { sB[tid] = bu1[tid]; sA[tid] = au1[tid]; }
    __syncthreads();
    // stage 3: u1 = prelu([rec, bin*256]@Wu1 + b) -> Ht
    zero_acc(acc);
    gemm64(Xt, Wb, ty, tx, acc);
    {
        const float* ap2 = Bt + ty * 8;
        const float* wp2 = Wb + 64 * WP + tx * 8;
#pragma unroll
        for (int k = 0; k < 8; k++) {
            float4 a0 = ld4(ap2 + k * AP);
            float4 a1 = ld4(ap2 + k * AP + 4);
            float4 w0 = ld4(wp2 + k * WP);
            float4 w1 = ld4(wp2 + k * WP + 4);
            float av[8] = {a0.x, a0.y, a0.z, a0.w, a1.x, a1.y, a1.z, a1.w};
            float wv[8] = {w0.x, w0.y, w0.z, w0.w, w1.x, w1.y, w1.z, w1.w};
#pragma unroll
            for (int i = 0; i < 8; i++)
#pragma unroll
                for (int j = 0; j < 8; j++)
                    acc[i][j] += av[i] * wv[j];
        }
    }
    epi_prelu_T(acc, sB, sA, Ht, ty, tx);
    __syncthreads();
    load_w(Wb, Wu2, 64, tid);
    if (tid < 64) { sB[tid] = bu2[tid]; sA[tid] = au2[tid]; }
    __syncthreads();
    // stage 4: h2 = prelu(u1@Wu2 + b) -> Xt
    zero_acc(acc);
    gemm64(Ht, Wb, ty, tx, acc);
    epi_prelu_T(acc, sB, sA, Xt, ty, tx);
    __syncthreads();
    load_w(Wb, Wu3, 64, tid);
    if (tid < 64) sB[tid] = bu3[tid];
    __syncthreads();
    // stage 5: u = u1 + h2@Wu3 + b -> g_u
    zero_acc(acc);
    gemm64(Xt, Wb, ty, tx, acc);
    epi_res_gstore(acc, sB, Ht, nullptr, g_u, base, ty, tx);
}

// ---------------- K2: pred head (rec -> [N,255]) ----------------
__global__ __launch_bounds__(NT, 1)
void k2_pred(const float* __restrict__ Wp1, const float* __restrict__ bp1, const float* __restrict__ ap_,
             const float* __restrict__ Wp2, const float* __restrict__ bp2,
             float* __restrict__ pred_out) {
    extern __shared__ float sm[];
    float* Xt = sm;              // 17408 floats region: Xt [64][AP], later Obuf [256][68]
    float* Ht = Xt + 17408;      // [64][AP]
    float* Wb = Ht + 64 * AP;    // [64][WP]
    float* sB = Wb + 64 * WP;    // 256
    float* sA = sB + 256;        // 64

    int tid = threadIdx.x;
    int ty = tid >> 3, tx = tid & 7;
    int base = blockIdx.x * ROWS;

    load_tileT(Xt, g_rec, base, tid);
    load_w(Wb, Wp1, 64, tid);
    if (tid < 64) { sB[tid] = bp1[tid]; sA[tid] = ap_[tid]; }
    __syncthreads();

    float acc[8][8];
    zero_acc(acc);
    gemm64(Xt, Wb, ty, tx, acc);
    epi_prelu_T(acc, sB, sA, Ht, ty, tx);   // p -> Ht
    __syncthreads();

    float* Ob = Xt;  // rec dead; reuse as [256][68] output staging
    for (int cc = 0; cc < 4; cc++) {
        int o0 = cc * 64;
        int w = 255 - o0; if (w > 64) w = 64;
        for (int lin = tid; lin < 4096; lin += NT) {
            int k = lin >> 6, c = lin & 63;
            Wb[k * WP + c] = (c < w) ? Wp2[(size_t)k * 255 + o0 + c] : 0.f;
        }
        if (tid < 64) sB[tid] = (tid < w) ? bp2[o0 + tid] : 0.f;
        __syncthreads();
        zero_acc(acc);
        gemm64(Ht, Wb, ty, tx, acc);
#pragma unroll
        for (int i = 0; i < 8; i++) {
            int r = ty * 8 + i;
            float v[8];
#pragma unroll
            for (int j = 0; j < 8; j++) v[j] = acc[i][j] + sB[tx * 8 + j];
            st4(&Ob[r * 68 + tx * 8],     make_float4(v[0], v[1], v[2], v[3]));
            st4(&Ob[r * 68 + tx * 8 + 4], make_float4(v[4], v[5], v[6], v[7]));
        }
        __syncthreads();
        int tot = ROWS * w;
        for (int lin = tid; lin < tot; lin += NT) {
            int r = lin / w, c = lin - r * w;
            pred_out[(size_t)(base + r) * 255 + o0 + c] = Ob[r * 68 + c];
        }
        __syncthreads();
    }
}

// ---------------- K3: final up linear + child scatter ----------------
__global__ __launch_bounds__(NT, 1)
void k3_up4(const int* __restrict__ bin, const float* __restrict__ Wu4, const float* __restrict__ bu4,
            float* __restrict__ newF) {
    extern __shared__ float sm[];
    float* Xt = sm;              // [64][AP] u transposed
    float* Wb = Xt + 64 * AP;    // [64][WP]
    float* sB = Wb + 64 * WP;    // 64
    int* Bs = (int*)(sB + 64);   // [256][8] bin
    int* Is = Bs + ROWS * 8;     // [256][8] inverse map

    int tid = threadIdx.x;
    int ty = tid >> 3, tx = tid & 7;
    int base = blockIdx.x * ROWS;

    load_tileT(Xt, g_u, base, tid);
    for (int lin = tid; lin < ROWS * 8; lin += NT) {
        Bs[lin] = bin[(size_t)base * 8 + lin];
        Is[lin] = g_inv[(size_t)base * 8 + lin];
    }
    for (int ch = 0; ch < 8; ch++) {
        if (ch) __syncthreads();  // guard Wb reuse across children
        for (int lin = tid; lin < 4096; lin += NT) {
            int k = lin >> 6, c = lin & 63;
            Wb[k * WP + c] = Wu4[(size_t)k * 512 + ch * 64 + c];
        }
        if (tid < 64) sB[tid] = bu4[ch * 64 + tid];
        __syncthreads();  // also covers Xt/Bs/Is loads on first iteration
        float acc[8][8];
        zero_acc(acc);
        gemm64(Xt, Wb, ty, tx, acc);
#pragma unroll
        for (int i = 0; i < 8; i++) {
            int r = ty * 8 + i;
            if (Bs[r * 8 + ch]) {
                int m = Is[r * 8 + ch];
                float v[8];
#pragma unroll
                for (int j = 0; j < 8; j++) v[j] = acc[i][j] + sB[tx * 8 + j];
                st4(&newF[(size_t)m * 64 + tx * 8],     make_float4(v[0], v[1], v[2], v[3]));
                st4(&newF[(size_t)m * 64 + tx * 8 + 4], make_float4(v[4], v[5], v[6], v[7]));
            }
        }
    }
}

extern "C" void kernel_launch(void* const* d_in, const int* in_sizes, int n_in,
                              void* d_out, int out_size) {
    const float* X   = (const float*)d_in[0];
    const int*   bin = (const int*)d_in[1];
    const int*   sel = (const int*)d_in[2];
    const float* Wd1 = (const float*)d_in[3];
    const float* bd1 = (const float*)d_in[4];
    const float* ad  = (const float*)d_in[5];
    const float* Wd2 = (const float*)d_in[6];
    const float* bd2 = (const float*)d_in[7];
    const float* Wp1 = (const float*)d_in[8];
    const float* bp1 = (const float*)d_in[9];
    const float* ap  = (const float*)d_in[10];
    const float* Wp2 = (const float*)d_in[11];
    const float* bp2 = (const float*)d_in[12];
    const float* Wu1 = (const float*)d_in[13];
    const float* bu1 = (const float*)d_in[14];
    const float* au1 = (const float*)d_in[15];
    const float* Wu2 = (const float*)d_in[16];
    const float* bu2 = (const float*)d_in[17];
    const float* au2 = (const float*)d_in[18];
    const float* Wu3 = (const float*)d_in[19];
    const float* bu3 = (const float*)d_in[20];
    const float* Wu4 = (const float*)d_in[21];
    const float* bu4 = (const float*)d_in[22];

    int n = in_sizes[0] / 64;   // number of nodes (262144)
    int M = in_sizes[2];        // selected children
    float* newF = (float*)d_out;
    float* pred = newF + (size_t)M * 64;
    float* oct  = pred + (size_t)n * 255;

    size_t sm1 = (size_t)(64 * AP + 64 * AP + 8 * AP + 72 * WP + 128) * sizeof(float);
    size_t sm2 = (size_t)(17408 + 64 * AP + 64 * WP + 256 + 64) * sizeof(float);
    size_t sm3 = (size_t)(64 * AP + 64 * WP + 64) * sizeof(float) + (size_t)ROWS * 8 * 2 * sizeof(int);

    cudaFuncSetAttribute(k1_dec_up, cudaFuncAttributeMaxDynamicSharedMemorySize, (int)sm1);
    cudaFuncSetAttribute(k2_pred,   cudaFuncAttributeMaxDynamicSharedMemorySize, (int)sm2);
    cudaFuncSetAttribute(k3_up4,    cudaFuncAttributeMaxDynamicSharedMemorySize, (int)sm3);

    int blocks = n / ROWS;
    if (M > 0) k0_inv<<<(M + 255) / 256, 256>>>(sel, M);
    k1_dec_up<<<blocks, NT, sm1>>>(X, bin, Wd1, bd1, ad, Wd2, bd2,
                                   Wu1, bu1, au1, Wu2, bu2, au2, Wu3, bu3, oct);
    k2_pred<<<blocks, NT, sm2>>>(Wp1, bp1, ap, Wp2, bp2, pred);
    k3_up4<<<blocks, NT, sm3>>>(bin, Wu4, bu4, newF);
}

// round 2
// speedup vs baseline: 1.0030x; 1.0030x over previous
#include <cuda_runtime.h>
#include <cstdint>

#define NNODES 262144
#define ROWS 256
#define NT 256
#define AP 264   // transposed activation tile row stride (floats), 64 x AP
#define WP 68    // weight buffer row stride (floats)

// Scratch (static device globals: allowed; no runtime allocation)
__device__ float g_rec[(size_t)NNODES * 64];
__device__ float g_u[(size_t)NNODES * 64];
__device__ int   g_inv[(size_t)NNODES * 8];

static __device__ __forceinline__ float4 ld4(const float* p) { return *(const float4*)p; }
static __device__ __forceinline__ void st4(float* p, float4 v) { *(float4*)p = v; }

static __device__ __forceinline__ void zero_acc(float acc[8][8]) {
#pragma unroll
    for (int i = 0; i < 8; i++)
#pragma unroll
        for (int j = 0; j < 8; j++) acc[i][j] = 0.f;
}

// C[256x64] += At(k-major [64][AP]) * Wb([64][WP]); 8x8 frag per thread.
static __device__ __forceinline__ void gemm64(const float* __restrict__ At,
                                              const float* __restrict__ Wb,
                                              int ty, int tx, float acc[8][8]) {
    const float* ap = At + ty * 8;
    const float* wp = Wb + tx * 8;
#pragma unroll 4
    for (int k = 0; k < 64; k++) {
        float4 a0 = ld4(ap + k * AP);
        float4 a1 = ld4(ap + k * AP + 4);
        float4 w0 = ld4(wp + k * WP);
        float4 w1 = ld4(wp + k * WP + 4);
        float av[8] = {a0.x, a0.y, a0.z, a0.w, a1.x, a1.y, a1.z, a1.w};
        float wv[8] = {w0.x, w0.y, w0.z, w0.w, w1.x, w1.y, w1.z, w1.w};
#pragma unroll
        for (int i = 0; i < 8; i++)
#pragma unroll
            for (int j = 0; j < 8; j++)
                acc[i][j] += av[i] * wv[j];
    }
}

// Load a [256 x 64] row-major global tile and store transposed (k-major) into smem.
static __device__ __forceinline__ void load_tileT(float* Xt, const float* __restrict__ src,
                                                  int base, int tid) {
#pragma unroll
    for (int q = 0; q < 16; q++) {
        int lin = (q * NT + tid) * 4;
        int row = lin >> 6, k = lin & 63;
        float4 v = ld4(src + (size_t)(base + row) * 64 + k);
        Xt[(k + 0) * AP + row] = v.x;
        Xt[(k + 1) * AP + row] = v.y;
        Xt[(k + 2) * AP + row] = v.z;
        Xt[(k + 3) * AP + row] = v.w;
    }
}

static __device__ __forceinline__ void load_w(float* Wb, const float* __restrict__ W, int K, int tid) {
    for (int lin = tid; lin < K * 64; lin += NT)
        Wb[(lin >> 6) * WP + (lin & 63)] = W[lin];
}

// y = prelu(acc + b, a), stored transposed (k-major) into Dst.
static __device__ __forceinline__ void epi_prelu_T(float acc[8][8], const float* sB, const float* sA,
                                                   float* Dst, int ty, int tx) {
#pragma unroll
    for (int j = 0; j < 8; j++) {
        int c = tx * 8 + j;
        float b = sB[c], a = sA[c];
        float t0[8];
#pragma unroll
        for (int i = 0; i < 8; i++) {
            float v = acc[i][j] + b;
            t0[i] = v >= 0.f ? v : a * v;
        }
        st4(&Dst[c * AP + ty * 8],     make_float4(t0[0], t0[1], t0[2], t0[3]));
        st4(&Dst[c * AP + ty * 8 + 4], make_float4(t0[4], t0[5], t0[6], t0[7]));
    }
}

// y = acc + b + Res (residual read transposed); optionally also store transposed into AlsoT;
// always store row-major to gOut (coalesced float4 stores).
static __device__ __forceinline__ void epi_res_gstore(float acc[8][8], const float* sB,
                                                      const float* Res, float* AlsoT,
                                                      float* __restrict__ gOut, int base,
                                                      int ty, int tx) {
#pragma unroll
    for (int j = 0; j < 8; j++) {
        int c = tx * 8 + j;
        float b = sB[c];
        float4 r0 = ld4(&Res[c * AP + ty * 8]);
        float4 r1 = ld4(&Res[c * AP + ty * 8 + 4]);
        acc[0][j] += b + r0.x; acc[1][j] += b + r0.y; acc[2][j] += b + r0.z; acc[3][j] += b + r0.w;
        acc[4][j] += b + r1.x; acc[5][j] += b + r1.y; acc[6][j] += b + r1.z; acc[7][j] += b + r1.w;
        if (AlsoT) {
            st4(&AlsoT[c * AP + ty * 8],     make_float4(acc[0][j], acc[1][j], acc[2][j], acc[3][j]));
            st4(&AlsoT[c * AP + ty * 8 + 4], make_float4(acc[4][j], acc[5][j], acc[6][j], acc[7][j]));
        }
    }
#pragma unroll
    for (int i = 0; i < 8; i++) {
        int r = ty * 8 + i;
        st4(&gOut[(size_t)(base + r) * 64 + tx * 8],
            make_float4(acc[i][0], acc[i][1], acc[i][2], acc[i][3]));
        st4(&gOut[(size_t)(base + r) * 64 + tx * 8 + 4],
            make_float4(acc[i][4], acc[i][5], acc[i][6], acc[i][7]));
    }
}

// ---------------- K0: inverse map of sel_idx ----------------
__global__ void k0_inv(const int* __restrict__ sel, int M) {
    int m = blockIdx.x * 256 + threadIdx.x;
    if (m < M) g_inv[sel[m]] = m;
}

// ---------------- K1: dec resblock + oct + upsample front (u) ----------------
__global__ __launch_bounds__(NT, 1)
void k1_dec_up(const float* __restrict__ X, const int* __restrict__ bin,
               const float* __restrict__ Wd1, const float* __restrict__ bd1, const float* __restrict__ ad,
               const float* __restrict__ Wd2, const float* __restrict__ bd2,
               const float* __restrict__ Wu1, const float* __restrict__ bu1, const float* __restrict__ au1,
               const float* __restrict__ Wu2, const float* __restrict__ bu2, const float* __restrict__ au2,
               const float* __restrict__ Wu3, const float* __restrict__ bu3,
               float* __restrict__ oct_out) {
    extern __shared__ float sm[];
    float* Xt = sm;              // [64][AP]
    float* Ht = Xt + 64 * AP;    // [64][AP]
    float* Bt = Ht + 64 * AP;    // [8][AP]  bin * 256 (transposed)
    float* Wb = Bt + 8 * AP;     // [72][WP]
    float* sB = Wb + 72 * WP;    // 64
    float* sA = sB + 64;         // 64

    int tid = threadIdx.x;
    int ty = tid >> 3, tx = tid & 7;
    int base = blockIdx.x * ROWS;

    load_tileT(Xt, X, base, tid);
#pragma unroll
    for (int q = 0; q < 8; q++) {
        int lin = q * NT + tid;
        Bt[(lin & 7) * AP + (lin >> 3)] = (float)(bin[(size_t)base * 8 + lin] << 8);
    }
    load_w(Wb, Wd1, 64, tid);
    if (tid < 64) { sB[tid] = bd1[tid]; sA[tid] = ad[tid]; }
    __syncthreads();

    // cur_oct (one row per thread)
    {
        int oct = -1;
#pragma unroll
        for (int j = 0; j < 8; j++)
            if (Bt[j * AP + tid] != 0.f) oct += (1 << j);
        oct_out[base + tid] = (float)oct;
    }

    float acc[8][8];
    // stage 1: h = prelu(X@Wd1 + b) -> Ht
    zero_acc(acc);
    gemm64(Xt, Wb, ty, tx, acc);
    epi_prelu_T(acc, sB, sA, Ht, ty, tx);
    __syncthreads();
    load_w(Wb, Wd2, 64, tid);
    if (tid < 64) sB[tid] = bd2[tid];
    __syncthreads();
    // stage 2: rec = X + h@Wd2 + b -> Xt (in place) and g_rec
    zero_acc(acc);
    gemm64(Ht, Wb, ty, tx, acc);
    epi_res_gstore(acc, sB, Xt, Xt, g_rec, base, ty, tx);
    __syncthreads();
    load_w(Wb, Wu1, 72, tid);
    if (tid < 64) { sB[tid] = bu1[tid]; sA[tid] = au1[tid]; }
    __syncthreads();
    // stage 3: u1 = prelu([rec, bin*256]@Wu1 + b) -> Ht
    zero_acc(acc);
    gemm64(Xt, Wb, ty, tx, acc);
    {
        const float* ap2 = Bt + ty * 8;
        const float* wp2 = Wb + 64 * WP + tx * 8;
#pragma unroll
        for (int k = 0; k < 8; k++) {
            float4 a0 = ld4(ap2 + k * AP);
            float4 a1 = ld4(ap2 + k * AP + 4);
            float4 w0 = ld4(wp2 + k * WP);
            float4 w1 = ld4(wp2 + k * WP + 4);
            float av[8] = {a0.x, a0.y, a0.z, a0.w, a1.x, a1.y, a1.z, a1.w};
            float wv[8] = {w0.x, w0.y, w0.z, w0.w, w1.x, w1.y, w1.z, w1.w};
#pragma unroll
            for (int i = 0; i < 8; i++)
#pragma unroll
                for (int j = 0; j < 8; j++)
                    acc[i][j] += av[i] * wv[j];
        }
    }
    epi_prelu_T(acc, sB, sA, Ht, ty, tx);
    __syncthreads();
    load_w(Wb, Wu2, 64, tid);
    if (tid < 64) { sB[tid] = bu2[tid]; sA[tid] = au2[tid]; }
    __syncthreads();
    // stage 4: h2 = prelu(u1@Wu2 + b) -> Xt
    zero_acc(acc);
    gemm64(Ht, Wb, ty, tx, acc);
    epi_prelu_T(acc, sB, sA, Xt, ty, tx);
    __syncthreads();
    load_w(Wb, Wu3, 64, tid);
    if (tid < 64) sB[tid] = bu3[tid];
    __syncthreads();
    // stage 5: u = u1 + h2@Wu3 + b -> g_u
    zero_acc(acc);
    gemm64(Xt, Wb, ty, tx, acc);
    epi_res_gstore(acc, sB, Ht, nullptr, g_u, base, ty, tx);
}

// ---------------- K2: pred head (rec -> [N,255]) ----------------
__global__ __launch_bounds__(NT, 1)
void k2_pred(const float* __restrict__ Wp1, const float* __restrict__ bp1, const float* __restrict__ ap_,
             const float* __restrict__ Wp2, const float* __restrict__ bp2,
             float* __restrict__ pred_out) {
    extern __shared__ float sm[];
    float* Xt = sm;              // 17408 floats region: Xt [64][AP], later Obuf [256][68]
    float* Ht = Xt + 17408;      // [64][AP]
    float* Wb = Ht + 64 * AP;    // [64][WP]
    float* sB = Wb + 64 * WP;    // 256
    float* sA = sB + 256;        // 64

    int tid = threadIdx.x;
    int ty = tid >> 3, tx = tid & 7;
    int base = blockIdx.x * ROWS;

    load_tileT(Xt, g_rec, base, tid);
    load_w(Wb, Wp1, 64, tid);
    if (tid < 64) { sB[tid] = bp1[tid]; sA[tid] = ap_[tid]; }
    __syncthreads();

    float acc[8][8];
    zero_acc(acc);
    gemm64(Xt, Wb, ty, tx, acc);
    epi_prelu_T(acc, sB, sA, Ht, ty, tx);   // p -> Ht
    __syncthreads();

    float* Ob = Xt;  // rec dead; reuse as [256][68] output staging
    for (int cc = 0; cc < 4; cc++) {
        int o0 = cc * 64;
        int w = 255 - o0; if (w > 64) w = 64;
        for (int lin = tid; lin < 4096; lin += NT) {
            int k = lin >> 6, c = lin & 63;
            Wb[k * WP + c] = (c < w) ? Wp2[(size_t)k * 255 + o0 + c] : 0.f;
        }
        if (tid < 64) sB[tid] = (tid < w) ? bp2[o0 + tid] : 0.f;
        __syncthreads();
        zero_acc(acc);
        gemm64(Ht, Wb, ty, tx, acc);
#pragma unroll
        for (int i = 0; i < 8; i++) {
            int r = ty * 8 + i;
            float v[8];
#pragma unroll
            for (int j = 0; j < 8; j++) v[j] = acc[i][j] + sB[tx * 8 + j];
            st4(&Ob[r * 68 + tx * 8],     make_float4(v[0], v[1], v[2], v[3]));
            st4(&Ob[r * 68 + tx * 8 + 4], make_float4(v[4], v[5], v[6], v[7]));
        }
        __syncthreads();
        int tot = ROWS * w;
        for (int lin = tid; lin < tot; lin += NT) {
            int r = lin / w, c = lin - r * w;
            pred_out[(size_t)(base + r) * 255 + o0 + c] = Ob[r * 68 + c];
        }
        __syncthreads();
    }
}

// ---------------- K3: final up linear + child scatter ----------------
__global__ __launch_bounds__(NT, 1)
void k3_up4(const int* __restrict__ bin, const float* __restrict__ Wu4, const float* __restrict__ bu4,
            float* __restrict__ newF) {
    extern __shared__ float sm[];
    float* Xt = sm;              // [64][AP] u transposed
    float* Wb = Xt + 64 * AP;    // [64][WP]
    float* sB = Wb + 64 * WP;    // 64
    int* Bs = (int*)(sB + 64);   // [256][8] bin
    int* Is = Bs + ROWS * 8;     // [256][8] inverse map

    int tid = threadIdx.x;
    int ty = tid >> 3, tx = tid & 7;
    int base = blockIdx.x * ROWS;

    load_tileT(Xt, g_u, base, tid);
    for (int lin = tid; lin < ROWS * 8; lin += NT) {
        Bs[lin] = bin[(size_t)base * 8 + lin];
        Is[lin] = g_inv[(size_t)base * 8 + lin];
    }
    for (int ch = 0; ch < 8; ch++) {
        if (ch) __syncthreads();  // guard Wb reuse across children
        for (int lin = tid; lin < 4096; lin += NT) {
            int k = lin >> 6, c = lin & 63;
            Wb[k * WP + c] = Wu4[(size_t)k * 512 + ch * 64 + c];
        }
        if (tid < 64) sB[tid] = bu4[ch * 64 + tid];
        __syncthreads();  // also covers Xt/Bs/Is loads on first iteration
        float acc[8][8];
        zero_acc(acc);
        gemm64(Xt, Wb, ty, tx, acc);
#pragma unroll
        for (int i = 0; i < 8; i++) {
            int r = ty * 8 + i;
            if (Bs[r * 8 + ch]) {
                int m = Is[r * 8 + ch];
                float v[8];
#pragma unroll
                for (int j = 0; j < 8; j++) v[j] = acc[i][j] + sB[tx * 8 + j];
                st4(&newF[(size_t)m * 64 + tx * 8],     make_float4(v[0], v[1], v[2], v[3]));
                st4(&newF[(size_t)m * 64 + tx * 8 + 4], make_float4(v[4], v[5], v[6], v[7]));
            }
        }
    }
}

extern "C" void kernel_launch(void* const* d_in, const int* in_sizes, int n_in,
                              void* d_out, int out_size) {
    const float* X   = (const float*)d_in[0];
    const int*   bin = (const int*)d_in[1];
    const int*   sel = (const int*)d_in[2];
    const float* Wd1 = (const float*)d_in[3];
    const float* bd1 = (const float*)d_in[4];
    const float* ad  = (const float*)d_in[5];
    const float* Wd2 = (const float*)d_in[6];
    const float* bd2 = (const float*)d_in[7];
    const float* Wp1 = (const float*)d_in[8];
    const float* bp1 = (const float*)d_in[9];
    const float* ap  = (const float*)d_in[10];
    const float* Wp2 = (const float*)d_in[11];
    const float* bp2 = (const float*)d_in[12];
    const float* Wu1 = (const float*)d_in[13];
    const float* bu1 = (const float*)d_in[14];
    const float* au1 = (const float*)d_in[15];
    const float* Wu2 = (const float*)d_in[16];
    const float* bu2 = (const float*)d_in[17];
    const float* au2 = (const float*)d_in[18];
    const float* Wu3 = (const float*)d_in[19];
    const float* bu3 = (const float*)d_in[20];
    const float* Wu4 = (const float*)d_in[21];
    const float* bu4 = (const float*)d_in[22];

    int n = in_sizes[0] / 64;   // number of nodes (262144)
    int M = in_sizes[2];        // selected children
    float* newF = (float*)d_out;
    float* pred = newF + (size_t)M * 64;
    float* oct  = pred + (size_t)n * 255;

    size_t sm1 = (size_t)(64 * AP + 64 * AP + 8 * AP + 72 * WP + 128) * sizeof(float);
    size_t sm2 = (size_t)(17408 + 64 * AP + 64 * WP + 256 + 64) * sizeof(float);
    size_t sm3 = (size_t)(64 * AP + 64 * WP + 64) * sizeof(float) + (size_t)ROWS * 8 * 2 * sizeof(int);

    cudaFuncSetAttribute(k1_dec_up, cudaFuncAttributeMaxDynamicSharedMemorySize, (int)sm1);
    cudaFuncSetAttribute(k2_pred,   cudaFuncAttributeMaxDynamicSharedMemorySize, (int)sm2);
    cudaFuncSetAttribute(k3_up4,    cudaFuncAttributeMaxDynamicSharedMemorySize, (int)sm3);

    int blocks = n / ROWS;
    if (M > 0) k0_inv<<<(M + 255) / 256, 256>>>(sel, M);
    k1_dec_up<<<blocks, NT, sm1>>>(X, bin, Wd1, bd1, ad, Wd2, bd2,
                                   Wu1, bu1, au1, Wu2, bu2, au2, Wu3, bu3, oct);
    k2_pred<<<blocks, NT, sm2>>>(Wp1, bp1, ap, Wp2, bp2, pred);
    k3_up4<<<blocks, NT, sm3>>>(bin, Wu4, bu4, newF);
}

// round 4
// speedup vs baseline: 2.0416x; 2.0356x over previous
#include <cuda_runtime.h>
#include <cuda_bf16.h>
#include <cstdint>

#define TILEM 128
#define NTHR  128
#define NJOBS 18
#define ARS   144      // activation/weight smem row stride (bytes)

// smem byte offsets
#define SM_A0H   0
#define SM_A0L   18432
#define SM_A1H   36864
#define SM_A1L   55296
#define SM_WH    73728
#define SM_WL    82944
#define SM_WTAIL 92160
#define SM_SB    94208
#define SM_SA    94464
#define SM_MASK  94720
#define SM_INV   95232
#define SM_TOTAL 99328

// pre-split weights, [job][n][k] packed 64x64 bf16
__device__ __align__(16) __nv_bfloat16 g_wh[NJOBS * 4096];
__device__ __align__(16) __nv_bfloat16 g_wl[NJOBS * 4096];
__device__ int g_inv[(size_t)262144 * 8];

static __device__ __forceinline__ uint32_t pkbf(__nv_bfloat16 a, __nv_bfloat16 b) {
    uint16_t ua = *(uint16_t*)&a, ub = *(uint16_t*)&b;
    return (uint32_t)ua | ((uint32_t)ub << 16);
}
static __device__ __forceinline__ float upk_lo(uint32_t u) {
    uint16_t t = (uint16_t)u; __nv_bfloat16 b = *(__nv_bfloat16*)&t; return __bfloat162float(b);
}
static __device__ __forceinline__ float upk_hi(uint32_t u) {
    uint16_t t = (uint16_t)(u >> 16); __nv_bfloat16 b = *(__nv_bfloat16*)&t; return __bfloat162float(b);
}
static __device__ __forceinline__ void spl(float v, __nv_bfloat16& h, __nv_bfloat16& l) {
    h = __float2bfloat16(v);
    l = __float2bfloat16(v - __bfloat162float(h));
}

static __device__ __forceinline__ void mma_bf16(float* c, const uint32_t* a, const uint32_t* b) {
    asm volatile(
        "mma.sync.aligned.m16n8k16.row.col.f32.bf16.bf16.f32 "
        "{%0,%1,%2,%3}, {%4,%5,%6,%7}, {%8,%9}, {%0,%1,%2,%3};"
        : "+f"(c[0]), "+f"(c[1]), "+f"(c[2]), "+f"(c[3])
        : "r"(a[0]), "r"(a[1]), "r"(a[2]), "r"(a[3]), "r"(b[0]), "r"(b[1]));
}

// ---------------- K_prep: split weights to bf16 hi/lo, [n][k] layout ----------------
__global__ void k_prep(const float* __restrict__ Wd1, const float* __restrict__ Wd2,
                       const float* __restrict__ Wp1, const float* __restrict__ Wp2,
                       const float* __restrict__ Wu1, const float* __restrict__ Wu2,
                       const float* __restrict__ Wu3, const float* __restrict__ Wu4) {
    int j = blockIdx.x;
    for (int t = threadIdx.x; t < 4096; t += 256) {
        int n = t >> 6, k = t & 63;
        float v;
        if (j == 0)      v = Wd1[k * 64 + n];
        else if (j == 1) v = Wd2[k * 64 + n];
        else if (j == 2) v = Wp1[k * 64 + n];
        else if (j <= 6) { int ng = (j - 3) * 64 + n; v = (ng < 255) ? Wp2[k * 255 + ng] : 0.f; }
        else if (j == 7) v = Wu1[k * 64 + n];        // rows 0..63 only; tail handled exactly
        else if (j == 8) v = Wu2[k * 64 + n];
        else if (j == 9) v = Wu3[k * 64 + n];
        else             v = Wu4[(size_t)k * 512 + (j - 10) * 64 + n];
        __nv_bfloat16 h, l; spl(v, h, l);
        g_wh[j * 4096 + t] = h;
        g_wl[j * 4096 + t] = l;
    }
}

// ---------------- K0: inverse map of sel_idx ----------------
__global__ void k0_inv(const int* __restrict__ sel, int M) {
    int m = blockIdx.x * 256 + threadIdx.x;
    if (m < M) g_inv[sel[m]] = m;
}

// ---------------- fused main kernel ----------------
__global__ __launch_bounds__(NTHR, 2)
void k_main(const float* __restrict__ X, const int* __restrict__ bin,
            const float* __restrict__ bd1, const float* __restrict__ ad,
            const float* __restrict__ bd2,
            const float* __restrict__ bp1, const float* __restrict__ ap_,
            const float* __restrict__ bp2,
            const float* __restrict__ bu1, const float* __restrict__ au1,
            const float* __restrict__ bu2, const float* __restrict__ au2,
            const float* __restrict__ bu3, const float* __restrict__ bu4,
            const float* __restrict__ Wu1,
            float* __restrict__ pred, float* __restrict__ oct, float* __restrict__ newF) {
    extern __shared__ char smem[];
    int tid = threadIdx.x;
    int wid = tid >> 5, lane = tid & 31;
    int g = lane >> 2, tg = lane & 3;
    int mrow = wid * 32;
    int base = blockIdx.x * TILEM;

    float* sB    = (float*)(smem + SM_SB);
    float* sA    = (float*)(smem + SM_SA);
    float* wtail = (float*)(smem + SM_WTAIL);
    int*   smask = (int*)(smem + SM_MASK);
    int*   sinv  = (int*)(smem + SM_INV);

    // ---- prologue: X -> R0 (split bf16), mask/inv/oct, Wu1 tail ----
    {
        const float4* Xr = (const float4*)(X + (size_t)base * 64);
#pragma unroll
        for (int it = 0; it < 16; it++) {
            int idx = it * NTHR + tid;            // 0..2047 float4s
            int row = idx >> 4, q = idx & 15;
            float4 v = Xr[idx];
            __nv_bfloat16 h0, h1, h2, h3, l0, l1, l2, l3;
            spl(v.x, h0, l0); spl(v.y, h1, l1); spl(v.z, h2, l2); spl(v.w, h3, l3);
            *(uint2*)(smem + SM_A0H + row * ARS + q * 8) = make_uint2(pkbf(h0, h1), pkbf(h2, h3));
            *(uint2*)(smem + SM_A0L + row * ARS + q * 8) = make_uint2(pkbf(l0, l1), pkbf(l2, l3));
        }
        const int* bp = bin + (size_t)(base + tid) * 8;
        int4 b0 = *(const int4*)bp;
        int4 b1 = *(const int4*)(bp + 4);
        int m = (b0.x != 0) | ((b0.y != 0) << 1) | ((b0.z != 0) << 2) | ((b0.w != 0) << 3)
              | ((b1.x != 0) << 4) | ((b1.y != 0) << 5) | ((b1.z != 0) << 6) | ((b1.w != 0) << 7);
        smask[tid] = m;
        oct[base + tid] = (float)(m - 1);
        const int* ip = g_inv + (size_t)(base + tid) * 8;
        int4 i0 = *(const int4*)ip;
        int4 i1 = *(const int4*)(ip + 4);
        *(int4*)(sinv + tid * 8)     = i0;
        *(int4*)(sinv + tid * 8 + 4) = i1;
#pragma unroll
        for (int it = 0; it < 4; it++)
            wtail[it * NTHR + tid] = Wu1[4096 + it * NTHR + tid];
    }

    for (int j = 0; j < NJOBS; j++) {
        __syncthreads();   // prev epilogue writes / prologue done before W overwrite
        // ---- load W tiles (hi/lo) + bias/prelu ----
        {
            const uint4* sh = (const uint4*)(g_wh + j * 4096);
            const uint4* sl = (const uint4*)(g_wl + j * 4096);
#pragma unroll
            for (int it = 0; it < 4; it++) {
                int i = it * NTHR + tid;          // 0..511 uint4s
                int row = i >> 3, c8 = i & 7;
                *(uint4*)(smem + SM_WH + row * ARS + c8 * 16) = sh[i];
                *(uint4*)(smem + SM_WL + row * ARS + c8 * 16) = sl[i];
            }
            if (tid < 64) {
                int c = tid;
                float b = 0.f, a = 0.25f;
                switch (j) {
                    case 0: b = bd1[c]; a = ad[c]; break;
                    case 1: b = bd2[c]; break;
                    case 2: b = bp1[c]; a = ap_[c]; break;
                    case 3: case 4: case 5: case 6: {
                        int ng = (j - 3) * 64 + c; b = (ng < 255) ? bp2[ng] : 0.f; break; }
                    case 7: b = bu1[c]; a = au1[c]; break;
                    case 8: b = bu2[c]; a = au2[c]; break;
                    case 9: b = bu3[c]; break;
                    default: b = bu4[(j - 10) * 64 + c]; break;
                }
                sB[c] = b; sA[c] = a;
            }
        }
        __syncthreads();

        // ---- GEMM: C[32x64] = A @ W (3-term bf16 split, fp32 accum) ----
        bool aR0 = (j == 0) | (j == 2) | (j == 7) | (j == 9);
        const char* aH = smem + (aR0 ? SM_A0H : SM_A1H);
        const char* aL = smem + (aR0 ? SM_A0L : SM_A1L);

        float cf[64];
#pragma unroll
        for (int i = 0; i < 64; i++) cf[i] = 0.f;

#pragma unroll
        for (int ks = 0; ks < 4; ks++) {
            int kb = ks * 32;
            uint32_t ah[2][4], al[2][4];
#pragma unroll
            for (int mt = 0; mt < 2; mt++) {
                const char* p0 = aH + (mrow + mt * 16 + g) * ARS + kb + tg * 4;
                const char* p1 = p0 + 8 * ARS;
                ah[mt][0] = *(const uint32_t*)p0;
                ah[mt][1] = *(const uint32_t*)p1;
                ah[mt][2] = *(const uint32_t*)(p0 + 16);
                ah[mt][3] = *(const uint32_t*)(p1 + 16);
                const char* q0 = aL + (mrow + mt * 16 + g) * ARS + kb + tg * 4;
                const char* q1 = q0 + 8 * ARS;
                al[mt][0] = *(const uint32_t*)q0;
                al[mt][1] = *(const uint32_t*)q1;
                al[mt][2] = *(const uint32_t*)(q0 + 16);
                al[mt][3] = *(const uint32_t*)(q1 + 16);
            }
            uint32_t wh[8][2], wl[8][2];
#pragma unroll
            for (int nt = 0; nt < 8; nt++) {
                const char* q = smem + SM_WH + (nt * 8 + g) * ARS + kb + tg * 4;
                wh[nt][0] = *(const uint32_t*)q;
                wh[nt][1] = *(const uint32_t*)(q + 16);
                const char* r = smem + SM_WL + (nt * 8 + g) * ARS + kb + tg * 4;
                wl[nt][0] = *(const uint32_t*)r;
                wl[nt][1] = *(const uint32_t*)(r + 16);
            }
#pragma unroll
            for (int nt = 0; nt < 8; nt++)
#pragma unroll
                for (int mt = 0; mt < 2; mt++) {
                    float* c = cf + mt * 32 + nt * 4;
                    mma_bf16(c, ah[mt], wh[nt]);
                    mma_bf16(c, ah[mt], wl[nt]);
                    mma_bf16(c, al[mt], wh[nt]);
                }
        }

        // ---- epilogue ----
        // bias
#pragma unroll
        for (int nt = 0; nt < 8; nt++) {
            float2 bb = *(const float2*)(sB + nt * 8 + tg * 2);
#pragma unroll
            for (int mt = 0; mt < 2; mt++) {
                float* c = cf + mt * 32 + nt * 4;
                c[0] += bb.x; c[1] += bb.y; c[2] += bb.x; c[3] += bb.y;
            }
        }
        // bin-concat tail (job 7): + 256 * Wu1[64+jj][col] for set bits (exact fp32)
        if (j == 7) {
#pragma unroll
            for (int mt = 0; mt < 2; mt++) {
                int rlo = mrow + mt * 16 + g;
                int ml = smask[rlo], mh = smask[rlo + 8];
#pragma unroll
                for (int jj = 0; jj < 8; jj++) {
                    bool bl = (ml >> jj) & 1, bh = (mh >> jj) & 1;
                    if (bl | bh) {
#pragma unroll
                        for (int nt = 0; nt < 8; nt++) {
                            float2 t = *(const float2*)(wtail + jj * 64 + nt * 8 + tg * 2);
                            float* c = cf + mt * 32 + nt * 4;
                            if (bl) { c[0] += 256.f * t.x; c[1] += 256.f * t.y; }
                            if (bh) { c[2] += 256.f * t.x; c[3] += 256.f * t.y; }
                        }
                    }
                }
            }
        }
        // prelu
        if (j == 0 || j == 2 || j == 7 || j == 8) {
#pragma unroll
            for (int nt = 0; nt < 8; nt++) {
                float2 aa = *(const float2*)(sA + nt * 8 + tg * 2);
#pragma unroll
                for (int mt = 0; mt < 2; mt++) {
                    float* c = cf + mt * 32 + nt * 4;
                    c[0] = c[0] >= 0.f ? c[0] : aa.x * c[0];
                    c[1] = c[1] >= 0.f ? c[1] : aa.y * c[1];
                    c[2] = c[2] >= 0.f ? c[2] : aa.x * c[2];
                    c[3] = c[3] >= 0.f ? c[3] : aa.y * c[3];
                }
            }
        }
        // residual (j1: +X in R0; j9: +u1 in R1) — sources == dst, per-thread positions
        if (j == 1 || j == 9) {
            const char* rH = smem + (j == 1 ? SM_A0H : SM_A1H);
            const char* rL = smem + (j == 1 ? SM_A0L : SM_A1L);
#pragma unroll
            for (int mt = 0; mt < 2; mt++) {
                int rlo = mrow + mt * 16 + g;
#pragma unroll
                for (int nt = 0; nt < 8; nt++) {
                    uint32_t off0 = rlo * ARS + nt * 16 + tg * 4;
                    uint32_t off1 = off0 + 8 * ARS;
                    uint32_t h0 = *(const uint32_t*)(rH + off0), l0 = *(const uint32_t*)(rL + off0);
                    uint32_t h1 = *(const uint32_t*)(rH + off1), l1 = *(const uint32_t*)(rL + off1);
                    float* c = cf + mt * 32 + nt * 4;
                    c[0] += upk_lo(h0) + upk_lo(l0);
                    c[1] += upk_hi(h0) + upk_hi(l0);
                    c[2] += upk_lo(h1) + upk_lo(l1);
                    c[3] += upk_hi(h1) + upk_hi(l1);
                }
            }
        }

        if (j >= 3 && j <= 6) {
            // pred chunk -> gmem (direct scalar stores)
            int o0 = (j - 3) * 64;
#pragma unroll
            for (int mt = 0; mt < 2; mt++) {
                int r0 = base + mrow + mt * 16 + g;
#pragma unroll
                for (int nt = 0; nt < 8; nt++) {
                    int col = o0 + nt * 8 + tg * 2;
                    float* c = cf + mt * 32 + nt * 4;
                    if (col < 255) {
                        pred[(size_t)r0 * 255 + col]       = c[0];
                        pred[(size_t)(r0 + 8) * 255 + col] = c[2];
                    }
                    if (col + 1 < 255) {
                        pred[(size_t)r0 * 255 + col + 1]       = c[1];
                        pred[(size_t)(r0 + 8) * 255 + col + 1] = c[3];
                    }
                }
            }
        } else if (j >= 10) {
            // child ch: stage fp32 in R0 (dead), then coalesced masked copy
            int ch = j - 10;
            float* stg = (float*)(smem + SM_A0H);   // [128][68]
#pragma unroll
            for (int mt = 0; mt < 2; mt++) {
                int rlo = mrow + mt * 16 + g;
#pragma unroll
                for (int nt = 0; nt < 8; nt++) {
                    int c0 = nt * 8 + tg * 2;
                    float* c = cf + mt * 32 + nt * 4;
                    *(float2*)(stg + rlo * 68 + c0)       = make_float2(c[0], c[1]);
                    *(float2*)(stg + (rlo + 8) * 68 + c0) = make_float2(c[2], c[3]);
                }
            }
            __syncthreads();
#pragma unroll
            for (int it = 0; it < 16; it++) {
                int lin = it * NTHR + tid;
                int row = lin >> 4, q = lin & 15;
                if ((smask[row] >> ch) & 1) {
                    float4 v = *(const float4*)(stg + row * 68 + q * 4);
                    *(float4*)(newF + (size_t)sinv[row * 8 + ch] * 64 + q * 4) = v;
                }
            }
        } else {
            // activation job: split-store to dst region (j1,j8 -> R0 else R1)
            bool dR0 = (j == 1) | (j == 8);
            char* dH = smem + (dR0 ? SM_A0H : SM_A1H);
            char* dL = smem + (dR0 ? SM_A0L : SM_A1L);
#pragma unroll
            for (int mt = 0; mt < 2; mt++) {
                int rlo = mrow + mt * 16 + g;
#pragma unroll
                for (int nt = 0; nt < 8; nt++) {
                    uint32_t off0 = rlo * ARS + nt * 16 + tg * 4;
                    uint32_t off1 = off0 + 8 * ARS;
                    float* c = cf + mt * 32 + nt * 4;
                    __nv_bfloat16 h0, h1, h2, h3, l0, l1, l2, l3;
                    spl(c[0], h0, l0); spl(c[1], h1, l1);
                    spl(c[2], h2, l2); spl(c[3], h3, l3);
                    *(uint32_t*)(dH + off0) = pkbf(h0, h1);
                    *(uint32_t*)(dL + off0) = pkbf(l0, l1);
                    *(uint32_t*)(dH + off1) = pkbf(h2, h3);
                    *(uint32_t*)(dL + off1) = pkbf(l2, l3);
                }
            }
        }
    }
}

extern "C" void kernel_launch(void* const* d_in, const int* in_sizes, int n_in,
                              void* d_out, int out_size) {
    const float* X   = (const float*)d_in[0];
    const int*   bin = (const int*)d_in[1];
    const int*   sel = (const int*)d_in[2];
    const float* Wd1 = (const float*)d_in[3];
    const float* bd1 = (const float*)d_in[4];
    const float* ad  = (const float*)d_in[5];
    const float* Wd2 = (const float*)d_in[6];
    const float* bd2 = (const float*)d_in[7];
    const float* Wp1 = (const float*)d_in[8];
    const float* bp1 = (const float*)d_in[9];
    const float* ap  = (const float*)d_in[10];
    const float* Wp2 = (const float*)d_in[11];
    const float* bp2 = (const float*)d_in[12];
    const float* Wu1 = (const float*)d_in[13];
    const float* bu1 = (const float*)d_in[14];
    const float* au1 = (const float*)d_in[15];
    const float* Wu2 = (const float*)d_in[16];
    const float* bu2 = (const float*)d_in[17];
    const float* au2 = (const float*)d_in[18];
    const float* Wu3 = (const float*)d_in[19];
    const float* bu3 = (const float*)d_in[20];
    const float* Wu4 = (const float*)d_in[21];
    const float* bu4 = (const float*)d_in[22];

    int n = in_sizes[0] / 64;
    int M = in_sizes[2];
    float* newF = (float*)d_out;
    float* pred = newF + (size_t)M * 64;
    float* oct  = pred + (size_t)n * 255;

    cudaFuncSetAttribute(k_main, cudaFuncAttributeMaxDynamicSharedMemorySize, SM_TOTAL);

    k_prep<<<NJOBS, 256>>>(Wd1, Wd2, Wp1, Wp2, Wu1, Wu2, Wu3, Wu4);
    if (M > 0) k0_inv<<<(M + 255) / 256, 256>>>(sel, M);
    k_main<<<n / TILEM, NTHR, SM_TOTAL>>>(X, bin, bd1, ad, bd2, bp1, ap, bp2,
                                          bu1, au1, bu2, au2, bu3, bu4, Wu1,
                                          pred, oct, newF);
}

// round 6
// speedup vs baseline: 3.0335x; 1.4859x over previous
#include <cuda_runtime.h>
#include <cuda_bf16.h>
#include <cstdint>

#define TILEM 128
#define NTHR  256
#define NJOBS 18
#define ARS   144      // smem row stride (bytes)

// smem byte offsets
#define SM_A0H   0
#define SM_A0L   18432
#define SM_A1H   36864
#define SM_A1L   55296
#define SM_WH    73728
#define SM_WL    82944
#define SM_WTAIL 92160
#define SM_SB    94208
#define SM_SA    94464
#define SM_MASK  94720
#define SM_INV   95232
#define SM_TOTAL 99328

// pre-split weights, [job][n][k] 64x64 bf16
__device__ __align__(16) __nv_bfloat16 g_wh[NJOBS * 4096];
__device__ __align__(16) __nv_bfloat16 g_wl[NJOBS * 4096];
__device__ int g_inv[(size_t)262144 * 8];

static __device__ __forceinline__ uint32_t smem_u32(const void* p) {
    uint32_t a;
    asm("{ .reg .u64 t; cvta.to.shared.u64 t, %1; cvt.u32.u64 %0, t; }" : "=r"(a) : "l"(p));
    return a;
}
static __device__ __forceinline__ uint32_t pkbf(__nv_bfloat16 a, __nv_bfloat16 b) {
    uint16_t ua = *(uint16_t*)&a, ub = *(uint16_t*)&b;
    return (uint32_t)ua | ((uint32_t)ub << 16);
}
static __device__ __forceinline__ float upk_lo(uint32_t u) {
    uint16_t t = (uint16_t)u; __nv_bfloat16 b = *(__nv_bfloat16*)&t; return __bfloat162float(b);
}
static __device__ __forceinline__ float upk_hi(uint32_t u) {
    uint16_t t = (uint16_t)(u >> 16); __nv_bfloat16 b = *(__nv_bfloat16*)&t; return __bfloat162float(b);
}
static __device__ __forceinline__ void spl(float v, __nv_bfloat16& h, __nv_bfloat16& l) {
    h = __float2bfloat16(v);
    l = __float2bfloat16(v - __bfloat162float(h));
}
static __device__ __forceinline__ void mma_bf16(float* c, const uint32_t* a, const uint32_t* b) {
    asm volatile(
        "mma.sync.aligned.m16n8k16.row.col.f32.bf16.bf16.f32 "
        "{%0,%1,%2,%3}, {%4,%5,%6,%7}, {%8,%9}, {%0,%1,%2,%3};"
        : "+f"(c[0]), "+f"(c[1]), "+f"(c[2]), "+f"(c[3])
        : "r"(a[0]), "r"(a[1]), "r"(a[2]), "r"(a[3]), "r"(b[0]), "r"(b[1]));
}
static __device__ __forceinline__ void ldm4(uint32_t* r, uint32_t addr) {
    asm volatile("ldmatrix.sync.aligned.m8n8.x4.shared.b16 {%0,%1,%2,%3}, [%4];"
        : "=r"(r[0]), "=r"(r[1]), "=r"(r[2]), "=r"(r[3]) : "r"(addr));
}

// ---------------- K_prep: split weights to bf16 hi/lo, [n][k] layout ----------------
__global__ void k_prep(const float* __restrict__ Wd1, const float* __restrict__ Wd2,
                       const float* __restrict__ Wp1, const float* __restrict__ Wp2,
                       const float* __restrict__ Wu1, const float* __restrict__ Wu2,
                       const float* __restrict__ Wu3, const float* __restrict__ Wu4) {
    int j = blockIdx.x;
    for (int t = threadIdx.x; t < 4096; t += 256) {
        int n = t >> 6, k = t & 63;
        float v;
        if (j == 0)      v = Wd1[k * 64 + n];
        else if (j == 1) v = Wd2[k * 64 + n];
        else if (j == 2) v = Wp1[k * 64 + n];
        else if (j <= 6) { int ng = (j - 3) * 64 + n; v = (ng < 255) ? Wp2[k * 255 + ng] : 0.f; }
        else if (j == 7) v = Wu1[k * 64 + n];
        else if (j == 8) v = Wu2[k * 64 + n];
        else if (j == 9) v = Wu3[k * 64 + n];
        else             v = Wu4[(size_t)k * 512 + (j - 10) * 64 + n];
        __nv_bfloat16 h, l; spl(v, h, l);
        g_wh[j * 4096 + t] = h;
        g_wl[j * 4096 + t] = l;
    }
}

// ---------------- K0: inverse map of sel_idx ----------------
__global__ void k0_inv(const int* __restrict__ sel, int M) {
    int m = blockIdx.x * 256 + threadIdx.x;
    if (m < M) g_inv[sel[m]] = m;
}

// ---------------- fused main kernel ----------------
__global__ __launch_bounds__(NTHR, 2)
void k_main(const float* __restrict__ X, const int* __restrict__ bin,
            const float* __restrict__ bd1, const float* __restrict__ ad,
            const float* __restrict__ bd2,
            const float* __restrict__ bp1, const float* __restrict__ ap_,
            const float* __restrict__ bp2,
            const float* __restrict__ bu1, const float* __restrict__ au1,
            const float* __restrict__ bu2, const float* __restrict__ au2,
            const float* __restrict__ bu3, const float* __restrict__ bu4,
            const float* __restrict__ Wu1,
            float* __restrict__ pred, float* __restrict__ oct, float* __restrict__ newF) {
    extern __shared__ char smem[];
    const uint32_t sb = smem_u32(smem);
    int tid = threadIdx.x;
    int wid = tid >> 5, lane = tid & 31;
    int g = lane >> 2, tg = lane & 3;
    int mrow = (wid >> 1) * 32;       // 4 m-quarters
    int ncol = (wid & 1) * 32;        // 2 n-halves
    int base = blockIdx.x * TILEM;

    float* sB    = (float*)(smem + SM_SB);
    float* sA    = (float*)(smem + SM_SA);
    float* wtail = (float*)(smem + SM_WTAIL);
    int*   smask = (int*)(smem + SM_MASK);
    int*   sinv  = (int*)(smem + SM_INV);

    // ---- prologue: X -> R0 (split bf16), mask/inv/oct, Wu1 tail ----
    {
        const float4* Xr = (const float4*)(X + (size_t)base * 64);
#pragma unroll
        for (int it = 0; it < 8; it++) {
            int idx = it * NTHR + tid;            // 0..2047 float4s
            int row = idx >> 4, q = idx & 15;
            float4 v = Xr[idx];
            __nv_bfloat16 h0, h1, h2, h3, l0, l1, l2, l3;
            spl(v.x, h0, l0); spl(v.y, h1, l1); spl(v.z, h2, l2); spl(v.w, h3, l3);
            *(uint2*)(smem + SM_A0H + row * ARS + q * 8) = make_uint2(pkbf(h0, h1), pkbf(h2, h3));
            *(uint2*)(smem + SM_A0L + row * ARS + q * 8) = make_uint2(pkbf(l0, l1), pkbf(l2, l3));
        }
        if (tid < TILEM) {
            const int* bp = bin + (size_t)(base + tid) * 8;
            int4 b0 = *(const int4*)bp;
            int4 b1 = *(const int4*)(bp + 4);
            int m = (b0.x != 0) | ((b0.y != 0) << 1) | ((b0.z != 0) << 2) | ((b0.w != 0) << 3)
                  | ((b1.x != 0) << 4) | ((b1.y != 0) << 5) | ((b1.z != 0) << 6) | ((b1.w != 0) << 7);
            smask[tid] = m;
            oct[base + tid] = (float)(m - 1);
            const int* ip = g_inv + (size_t)(base + tid) * 8;
            int4 i0 = *(const int4*)ip;
            int4 i1 = *(const int4*)(ip + 4);
            *(int4*)(sinv + tid * 8)     = i0;
            *(int4*)(sinv + tid * 8 + 4) = i1;
        }
#pragma unroll
        for (int it = 0; it < 2; it++)
            wtail[it * NTHR + tid] = Wu1[4096 + it * NTHR + tid];
    }

    // ---- weight/bias register prefetch (job 0) ----
    uint4 wr0, wr1, wr2, wr3;
    float bn = 0.f, an = 0.25f;
    {
        const uint4* sh = (const uint4*)(g_wh);
        const uint4* sl = (const uint4*)(g_wl);
        wr0 = sh[tid]; wr1 = sh[tid + 256];
        wr2 = sl[tid]; wr3 = sl[tid + 256];
        if (tid < 64) { bn = bd1[tid]; an = ad[tid]; }
    }

    // ldmatrix lane base offsets
    uint32_t aoff = (uint32_t)((mrow + (lane & 7) + ((lane >> 3) & 1) * 8) * ARS
                              + ((lane >> 4) & 1) * 16);
    uint32_t woff = (uint32_t)((ncol + (lane & 7) + ((lane >> 4) & 1) * 8) * ARS
                              + ((lane >> 3) & 1) * 16);
    uint32_t wHb = sb + SM_WH + woff;
    uint32_t wLb = sb + SM_WL + woff;

    for (int j = 0; j < NJOBS; j++) {
        __syncthreads();   // prior GEMM/epilogue complete
        // ---- commit prefetched W + bias to smem ----
        {
            int i0 = tid, i1 = tid + 256;
            *(uint4*)(smem + SM_WH + (i0 >> 3) * ARS + (i0 & 7) * 16) = wr0;
            *(uint4*)(smem + SM_WH + (i1 >> 3) * ARS + (i1 & 7) * 16) = wr1;
            *(uint4*)(smem + SM_WL + (i0 >> 3) * ARS + (i0 & 7) * 16) = wr2;
            *(uint4*)(smem + SM_WL + (i1 >> 3) * ARS + (i1 & 7) * 16) = wr3;
            if (tid < 64) { sB[tid] = bn; sA[tid] = an; }
        }
        __syncthreads();

        // ---- prefetch next job's W + bias into registers (hidden by GEMM) ----
        if (j + 1 < NJOBS) {
            int jn = j + 1;
            const uint4* sh = (const uint4*)(g_wh + jn * 4096);
            const uint4* sl = (const uint4*)(g_wl + jn * 4096);
            wr0 = sh[tid]; wr1 = sh[tid + 256];
            wr2 = sl[tid]; wr3 = sl[tid + 256];
            if (tid < 64) {
                int c = tid; float b = 0.f, a = 0.25f;
                switch (jn) {
                    case 1: b = bd2[c]; break;
                    case 2: b = bp1[c]; a = ap_[c]; break;
                    case 3: case 4: case 5: case 6: {
                        int ng = (jn - 3) * 64 + c; b = (ng < 255) ? bp2[ng] : 0.f; break; }
                    case 7: b = bu1[c]; a = au1[c]; break;
                    case 8: b = bu2[c]; a = au2[c]; break;
                    case 9: b = bu3[c]; break;
                    default: b = bu4[(jn - 10) * 64 + c]; break;
                }
                bn = b; an = a;
            }
        }

        // ---- GEMM: 3-term bf16-split, fp32 accum; warp tile m32 x n32 ----
        bool aR0 = (j == 0) | (j == 2) | (j == 7) | (j == 9);
        uint32_t aHb = sb + (aR0 ? SM_A0H : SM_A1H) + aoff;
        uint32_t aLb = aHb + 18432;

        float acc[2][4][4];
#pragma unroll
        for (int mt = 0; mt < 2; mt++)
#pragma unroll
            for (int nt = 0; nt < 4; nt++)
#pragma unroll
                for (int i = 0; i < 4; i++) acc[mt][nt][i] = 0.f;

#pragma unroll
        for (int kc = 0; kc < 4; kc++) {
            uint32_t ko = kc * 32;
            uint32_t ah[2][4], al[2][4], bh[2][4], bl[2][4];
            ldm4(ah[0], aHb + ko); ldm4(ah[1], aHb + ko + 16 * ARS);
            ldm4(al[0], aLb + ko); ldm4(al[1], aLb + ko + 16 * ARS);
            ldm4(bh[0], wHb + ko); ldm4(bh[1], wHb + ko + 16 * ARS);
            ldm4(bl[0], wLb + ko); ldm4(bl[1], wLb + ko + 16 * ARS);
#pragma unroll
            for (int p = 0; p < 2; p++)
#pragma unroll
                for (int h = 0; h < 2; h++) {
                    int nt = p * 2 + h;
                    const uint32_t* Bh = &bh[p][h * 2];
                    const uint32_t* Bl = &bl[p][h * 2];
#pragma unroll
                    for (int mt = 0; mt < 2; mt++) {
                        float* c = acc[mt][nt];
                        mma_bf16(c, ah[mt], Bh);
                        mma_bf16(c, ah[mt], Bl);
                        mma_bf16(c, al[mt], Bh);
                    }
                }
        }

        // ---- epilogue ----
#pragma unroll
        for (int mt = 0; mt < 2; mt++)
#pragma unroll
            for (int nt = 0; nt < 4; nt++) {
                int col = ncol + nt * 8 + tg * 2;
                float2 bb = *(const float2*)(sB + col);
                float* c = acc[mt][nt];
                c[0] += bb.x; c[1] += bb.y; c[2] += bb.x; c[3] += bb.y;
            }

        if (j == 7) {   // bin-concat tail: + 256 * Wu1[64+jj][col] for set bits (exact)
#pragma unroll
            for (int mt = 0; mt < 2; mt++) {
                int rA = mrow + mt * 16 + g;
                int mA = smask[rA], mB = smask[rA + 8];
#pragma unroll
                for (int jj = 0; jj < 8; jj++) {
                    bool bA = (mA >> jj) & 1, bB = (mB >> jj) & 1;
                    if (bA | bB) {
#pragma unroll
                        for (int nt = 0; nt < 4; nt++) {
                            float2 t = *(const float2*)(wtail + jj * 64 + ncol + nt * 8 + tg * 2);
                            float* c = acc[mt][nt];
                            if (bA) { c[0] += 256.f * t.x; c[1] += 256.f * t.y; }
                            if (bB) { c[2] += 256.f * t.x; c[3] += 256.f * t.y; }
                        }
                    }
                }
            }
        }
        if (j == 0 || j == 2 || j == 7 || j == 8) {  // prelu
#pragma unroll
            for (int mt = 0; mt < 2; mt++)
#pragma unroll
                for (int nt = 0; nt < 4; nt++) {
                    int col = ncol + nt * 8 + tg * 2;
                    float2 aa = *(const float2*)(sA + col);
                    float* c = acc[mt][nt];
                    c[0] = c[0] >= 0.f ? c[0] : aa.x * c[0];
                    c[1] = c[1] >= 0.f ? c[1] : aa.y * c[1];
                    c[2] = c[2] >= 0.f ? c[2] : aa.x * c[2];
                    c[3] = c[3] >= 0.f ? c[3] : aa.y * c[3];
                }
        }
        if (j == 1 || j == 9) {  // residual (j1: +X in R0; j9: +u1 in R1)
            const char* rH = smem + (j == 1 ? SM_A0H : SM_A1H);
            const char* rL = rH + 18432;
#pragma unroll
            for (int mt = 0; mt < 2; mt++) {
                int r = mrow + mt * 16 + g;
#pragma unroll
                for (int nt = 0; nt < 4; nt++) {
                    uint32_t off0 = r * ARS + (ncol + nt * 8 + tg * 2) * 2;
                    uint32_t off1 = off0 + 8 * ARS;
                    uint32_t h0 = *(const uint32_t*)(rH + off0), l0 = *(const uint32_t*)(rL + off0);
                    uint32_t h1 = *(const uint32_t*)(rH + off1), l1 = *(const uint32_t*)(rL + off1);
                    float* c = acc[mt][nt];
                    c[0] += upk_lo(h0) + upk_lo(l0);
                    c[1] += upk_hi(h0) + upk_hi(l0);
                    c[2] += upk_lo(h1) + upk_lo(l1);
                    c[3] += upk_hi(h1) + upk_hi(l1);
                }
            }
        }

        if (j >= 3 && j <= 6) {
            // pred -> gmem; row stride 255 floats is odd -> scalar 4B stores (alignment!)
            int o0 = (j - 3) * 64;
#pragma unroll
            for (int mt = 0; mt < 2; mt++) {
                int r = base + mrow + mt * 16 + g;
#pragma unroll
                for (int nt = 0; nt < 4; nt++) {
                    int col = o0 + ncol + nt * 8 + tg * 2;
                    float* c = acc[mt][nt];
                    float* p0 = pred + (size_t)r * 255 + col;
                    float* p1 = pred + (size_t)(r + 8) * 255 + col;
                    if (col < 255) { p0[0] = c[0]; p1[0] = c[2]; }
                    if (col + 1 < 255) { p0[1] = c[1]; p1[1] = c[3]; }
                }
            }
        } else if (j >= 10) {
            // child scatter -> newF (row stride 64 floats: float2 aligned)
            int ch = j - 10;
#pragma unroll
            for (int mt = 0; mt < 2; mt++) {
                int rA = mrow + mt * 16 + g;
                bool okA = (smask[rA] >> ch) & 1, okB = (smask[rA + 8] >> ch) & 1;
                int iA = sinv[rA * 8 + ch], iB = sinv[(rA + 8) * 8 + ch];
#pragma unroll
                for (int nt = 0; nt < 4; nt++) {
                    int col = ncol + nt * 8 + tg * 2;
                    float* c = acc[mt][nt];
                    if (okA) *(float2*)(newF + (size_t)iA * 64 + col) = make_float2(c[0], c[1]);
                    if (okB) *(float2*)(newF + (size_t)iB * 64 + col) = make_float2(c[2], c[3]);
                }
            }
        } else {
            // activation job: split-store to dst region (j1,j8 -> R0 else R1)
            bool dR0 = (j == 1) | (j == 8);
            char* dH = smem + (dR0 ? SM_A0H : SM_A1H);
            char* dL = dH + 18432;
#pragma unroll
            for (int mt = 0; mt < 2; mt++) {
                int r = mrow + mt * 16 + g;
#pragma unroll
                for (int nt = 0; nt < 4; nt++) {
                    uint32_t off0 = r * ARS + (ncol + nt * 8 + tg * 2) * 2;
                    uint32_t off1 = off0 + 8 * ARS;
                    float* c = acc[mt][nt];
                    __nv_bfloat16 h0, h1, h2, h3, l0, l1, l2, l3;
                    spl(c[0], h0, l0); spl(c[1], h1, l1);
                    spl(c[2], h2, l2); spl(c[3], h3, l3);
                    *(uint32_t*)(dH + off0) = pkbf(h0, h1);
                    *(uint32_t*)(dL + off0) = pkbf(l0, l1);
                    *(uint32_t*)(dH + off1) = pkbf(h2, h3);
                    *(uint32_t*)(dL + off1) = pkbf(l2, l3);
                }
            }
        }
    }
}

extern "C" void kernel_launch(void* const* d_in, const int* in_sizes, int n_in,
                              void* d_out, int out_size) {
    const float* X   = (const float*)d_in[0];
    const int*   bin = (const int*)d_in[1];
    const int*   sel = (const int*)d_in[2];
    const float* Wd1 = (const float*)d_in[3];
    const float* bd1 = (const float*)d_in[4];
    const float* ad  = (const float*)d_in[5];
    const float* Wd2 = (const float*)d_in[6];
    const float* bd2 = (const float*)d_in[7];
    const float* Wp1 = (const float*)d_in[8];
    const float* bp1 = (const float*)d_in[9];
    const float* ap  = (const float*)d_in[10];
    const float* Wp2 = (const float*)d_in[11];
    const float* bp2 = (const float*)d_in[12];
    const float* Wu1 = (const float*)d_in[13];
    const float* bu1 = (const float*)d_in[14];
    const float* au1 = (const float*)d_in[15];
    const float* Wu2 = (const float*)d_in[16];
    const float* bu2 = (const float*)d_in[17];
    const float* au2 = (const float*)d_in[18];
    const float* Wu3 = (const float*)d_in[19];
    const float* bu3 = (const float*)d_in[20];
    const float* Wu4 = (const float*)d_in[21];
    const float* bu4 = (const float*)d_in[22];

    int n = in_sizes[0] / 64;
    int M = in_sizes[2];
    float* newF = (float*)d_out;
    float* pred = newF + (size_t)M * 64;
    float* oct  = pred + (size_t)n * 255;

    cudaFuncSetAttribute(k_main, cudaFuncAttributeMaxDynamicSharedMemorySize, SM_TOTAL);

    k_prep<<<NJOBS, 256>>>(Wd1, Wd2, Wp1, Wp2, Wu1, Wu2, Wu3, Wu4);
    if (M > 0) k0_inv<<<(M + 255) / 256, 256>>>(sel, M);
    k_main<<<n / TILEM, NTHR, SM_TOTAL>>>(X, bin, bd1, ad, bd2, bp1, ap, bp2,
                                          bu1, au1, bu2, au2, bu3, bu4, Wu1,
                                          pred, oct, newF);
}